// round 11
// baseline (speedup 1.0000x reference)
#include <cuda_runtime.h>
#include <math.h>
#include <stdint.h>

// Problem constants
#define Hd 1024
#define Vd 4096
#define Bd 64
#define Td 512
#define BT (Bd*Td)       // 32768
#define BdHd (Bd*Hd)
#define NBLK 128         // 4 groups x 32 CTAs
#define GSZ 32           // CTAs per group
#define GROWS 16         // batch rows per group
#define JPC 32           // j columns per CTA

// Scratch (device globals; no runtime allocation)
__device__ float g_abase[(size_t)BT*Hd];   // (t,b,h) pre-activation x_emb + b
__device__ float g_hs[(size_t)BT*Hd];      // (t,b,h) hidden states
__device__ unsigned g_gcnt[4*32];          // atomic start-barrier counters (128B apart)
__device__ unsigned g_ggen[4*32];          // atomic start-barrier generations
__device__ __align__(128) unsigned g_flags[4*32];  // per-group arrival flags (one 128B line/group)

// ---------------------------------------------------------------------------
// K1: embedding gather + bias  a_base[(t*B+b), :] = wxh[X[b,t], :] + bvec
// ---------------------------------------------------------------------------
__global__ void embed_kernel(const int* __restrict__ X,
                             const float* __restrict__ wxh,
                             const float* __restrict__ bvec) {
    int r = blockIdx.x;            // r = t*B + b
    int t = r >> 6;
    int b = r & 63;
    int row = X[b * Td + t];
    const float4* src = (const float4*)(wxh + (size_t)row * Hd);
    const float4* bb  = (const float4*)bvec;
    float4* dst = (float4*)(g_abase + (size_t)r * Hd);
    int i = threadIdx.x;           // 256 = H/4
    float4 v = src[i];
    float4 w = bb[i];
    v.x += w.x; v.y += w.y; v.z += w.z; v.w += w.w;
    dst[i] = v;
}

// ---------------------------------------------------------------------------
// Atomic group barrier (launch-start only). Sense-reversing (count,gen) on
// group-private lines; replay-safe (self-resetting, equality compare).
// ---------------------------------------------------------------------------
__device__ __forceinline__ void group_barrier_atomic(int tid, int grp) {
    __syncthreads();
    if (tid == 0) {
        unsigned* cnt = &g_gcnt[grp * 32];
        unsigned* gnp = &g_ggen[grp * 32];
        unsigned gen = *(volatile unsigned*)gnp;
        __threadfence();
        unsigned p = atomicAdd(cnt, 1u);
        if (p == GSZ - 1u) {
            atomicExch(cnt, 0u);
            __threadfence();
            atomicExch(gnp, gen + 1u);
        } else {
            while (*(volatile unsigned*)gnp == gen) { }
        }
        __threadfence();
    }
    __syncthreads();
}

// ---------------------------------------------------------------------------
// K2: persistent recurrence, batch-partitioned groups, 1024 threads/CTA.
// Group g (32 CTAs) owns batch rows g*16..+16; CTA jc owns cols jc*32..+32
// with its W_hh slice (32x1024 = 128KB) resident in smem. 32 warps =
// 8(j-quad) x 4(b-quad); thread tile 4j x 4b; lanes split K 32 ways.
// Per step: flag poll-wait -> stage group h slice (64KB, coalesced LDG ->
// swizzled STS) -> FFMA partials -> merge+butterfly shuffle reduce ->
// tanh -> STG h -> post flag (plain store).
// Swizzle (f4 units): phys(u) = u ^ ((u>>3)&7), rows stride 256 f4.
// ---------------------------------------------------------------------------
__global__ void __launch_bounds__(1024, 1)
rnn_persistent(const float* __restrict__ whh) {
    extern __shared__ float4 dsm4[];
    float4* Wsl = dsm4;             // [32 rows][256 f4] swizzled  (128 KB)
    float4* hsm = dsm4 + 8192;      // [16 rows][256 f4] swizzled  (64 KB)

    const int bid = blockIdx.x;     // 0..127
    const int grp = bid >> 5;       // 0..3
    const int jc  = bid & 31;       // 0..31
    const int j0  = jc * JPC;
    const int b0  = grp * GROWS;
    const int tid = threadIdx.x;
    const int ln  = tid & 31;
    const int w   = tid >> 5;       // warp 0..31
    const int jw  = w >> 2;         // 0..7  (4 j-cols each)
    const int bw  = w & 3;          // 0..3  (4 b-rows each)

    // reset this CTA's arrival flag (made group-visible by the atomic barrier)
    if (tid == 0) *(volatile unsigned*)&g_flags[grp * 32 + jc] = 0u;

    // Load W_hh slice rows j0..j0+31 (contiguous) into swizzled smem
    {
        const float4* wsrc = (const float4*)(whh + (size_t)j0 * Hd);
        #pragma unroll
        for (int q = 0; q < 8; q++) {
            int idx = tid + q * 1024;            // 0..8191
            int r = idx >> 8, u = idx & 255;
            Wsl[r * 256 + (u ^ ((u >> 3) & 7))] = wsrc[idx];
        }
    }

    // h_0 = tanh(a_base[0]) for this CTA's owned (b,j): 16x32 = 512 elems
    if (tid < 512) {
        int r = tid >> 5, cc = tid & 31;
        size_t off = (size_t)(b0 + r) * Hd + j0 + cc;
        g_hs[off] = tanhf(g_abase[off]);
    }

    // everyone's flag reset + h init visible before the flag protocol starts
    group_barrier_atomic(tid, grp);

    // per-thread output coordinates: after reduce, lane ln (ln<16) owns
    // idx = ln&15 -> (m = idx>>2 j-col, i = idx&3 b-row)
    const int jo = j0 + jw * 4 + ((ln & 15) >> 2);
    const int bo = b0 + bw * 4 + (ln & 3);

    volatile unsigned* myflag = &g_flags[grp * 32 + jc];
    volatile unsigned* pollflag = &g_flags[grp * 32 + ln];

    for (int t = 1; t < Td; t++) {
        const unsigned local = (unsigned)(t - 1);   // completions so far

        // prefetch a_base for this thread's output (independent of barrier)
        float abv = __ldg(&g_abase[(size_t)t * BdHd + (size_t)bo * Hd + jo]);

        // wait: all 32 group flags >= local (warp 0 polls one 128B line)
        if (tid < 32) {
            while (__any_sync(0xffffffffu, *pollflag < local)) { }
            __threadfence();                     // acquire
        }
        __syncthreads();

        // stage group's h_{t-1} slice: 4096 f4, 4 per thread, coalesced
        {
            const float4* hsrc = (const float4*)(g_hs + (size_t)(t - 1) * BdHd
                                                      + (size_t)b0 * Hd);
            float4 pf[4];
            #pragma unroll
            for (int q = 0; q < 4; q++) pf[q] = hsrc[tid + q * 1024];
            #pragma unroll
            for (int q = 0; q < 4; q++) {
                int idx = tid + q * 1024;
                int r = idx >> 8, u = idx & 255;
                hsm[r * 256 + (u ^ ((u >> 3) & 7))] = pf[q];
            }
        }
        __syncthreads();

        // compute: thread covers j = jw*4..+4, b = bw*4..+4, k = ln*32..+32
        float acc[16];
        #pragma unroll
        for (int e = 0; e < 16; e++) acc[e] = 0.0f;

        #pragma unroll
        for (int kc = 0; kc < 8; kc++) {
            const int up = ln * 8 + (kc ^ (ln & 7));   // swizzled f4 col
            float4 wv[4];
            #pragma unroll
            for (int m = 0; m < 4; m++)
                wv[m] = Wsl[(jw * 4 + m) * 256 + up];
            #pragma unroll
            for (int i = 0; i < 4; i++) {
                float4 hv = hsm[(bw * 4 + i) * 256 + up];
                #pragma unroll
                for (int m = 0; m < 4; m++) {
                    float s = acc[m * 4 + i];
                    s = fmaf(hv.x, wv[m].x, s);
                    s = fmaf(hv.y, wv[m].y, s);
                    s = fmaf(hv.z, wv[m].z, s);
                    s = fmaf(hv.w, wv[m].w, s);
                    acc[m * 4 + i] = s;
                }
            }
        }

        // reduce: merge lane-halves (same 16 outputs, disjoint K), then
        // 4-round butterfly splits 16 outputs over 16 lanes.
        #pragma unroll
        for (int e = 0; e < 16; e++)
            acc[e] += __shfl_xor_sync(0xffffffffu, acc[e], 16);
        #pragma unroll
        for (int off = 8; off >= 1; off >>= 1) {
            #pragma unroll
            for (int i = 0; i < off; i++) {
                float send = (ln & off) ? acc[i] : acc[i + off];
                float keep = (ln & off) ? acc[i + off] : acc[i];
                acc[i] = keep + __shfl_xor_sync(0xffffffffu, send, off);
            }
        }
        // lane ln (and ln+16, duplicate) holds the K-sum for output (jo, bo)

        if (ln < 16)
            g_hs[(size_t)t * BdHd + (size_t)bo * Hd + jo] = tanhf(acc[0] + abv);

        // arrive: CTA's h_t stores done -> post flag (plain store, no RMW)
        __syncthreads();
        if (tid == 0) {
            __threadfence();                     // publish h_t
            *myflag = local + 1u;
        }
    }
}

// ---------------------------------------------------------------------------
// K4: output GEMM on tf32 tensor cores.
// z[r, v] = sum_k Hs[r,k] * Wvh[v,k] + c[v], row remap r=(t*B+b) -> (b*T+t).
// BM=128, BN=128, BK=16. 8 warps as 4(m) x 2(n); warp tile 32x64 =
// 2 x 8 tiles of m16n8k8. A row-major, B col-major (wvh rows ARE B columns).
// ---------------------------------------------------------------------------
__device__ __forceinline__ uint32_t f2tf32(float x) {
    uint32_t r;
    asm("cvt.rna.tf32.f32 %0, %1;" : "=r"(r) : "f"(x));
    return r;
}
__device__ __forceinline__ void mma_tf32(float c[4], uint32_t a0, uint32_t a1,
                                         uint32_t a2, uint32_t a3,
                                         uint32_t b0, uint32_t b1) {
    asm volatile(
        "mma.sync.aligned.m16n8k8.row.col.f32.tf32.tf32.f32 "
        "{%0,%1,%2,%3}, {%4,%5,%6,%7}, {%8,%9}, {%0,%1,%2,%3};"
        : "+f"(c[0]), "+f"(c[1]), "+f"(c[2]), "+f"(c[3])
        : "r"(a0), "r"(a1), "r"(a2), "r"(a3), "r"(b0), "r"(b1));
}

#define LDA 136   // pad: conflict-free fragment loads

__global__ void __launch_bounds__(256, 1)
vh_gemm_tf32(const float* __restrict__ wvh,
             const float* __restrict__ cvec,
             float* __restrict__ outp) {
    __shared__ uint32_t A_s[16][LDA];
    __shared__ uint32_t B_s[16][LDA];
    const int v0 = blockIdx.x * 128;
    const int r0 = blockIdx.y * 128;
    const int tid  = threadIdx.x;
    const int warp = tid >> 5;
    const int lane = tid & 31;
    const int warp_m = warp & 3;        // 4 m-warps
    const int warp_n = warp >> 2;       // 2 n-warps
    const int m_base = warp_m * 32;
    const int n_base = warp_n * 64;
    const int lq = lane >> 2;           // 0..7
    const int lr = lane & 3;            // 0..3

    float acc[2][8][4];
    #pragma unroll
    for (int mt = 0; mt < 2; mt++)
        #pragma unroll
        for (int nt = 0; nt < 8; nt++)
            #pragma unroll
            for (int e = 0; e < 4; e++) acc[mt][nt][e] = 0.0f;

    const int lrow = tid >> 2;          // 0..63
    const int lk4  = (tid & 3) * 4;

    for (int kc = 0; kc < 64; ++kc) {
        int k0 = kc * 16;
        float4 a0 = *(const float4*)(g_hs + (size_t)(r0 + lrow) * Hd + k0 + lk4);
        float4 a1 = *(const float4*)(g_hs + (size_t)(r0 + lrow + 64) * Hd + k0 + lk4);
        float4 b0 = *(const float4*)(wvh + (size_t)(v0 + lrow) * Hd + k0 + lk4);
        float4 b1 = *(const float4*)(wvh + (size_t)(v0 + lrow + 64) * Hd + k0 + lk4);
        __syncthreads();
        A_s[lk4 + 0][lrow] = f2tf32(a0.x); A_s[lk4 + 1][lrow] = f2tf32(a0.y);
        A_s[lk4 + 2][lrow] = f2tf32(a0.z); A_s[lk4 + 3][lrow] = f2tf32(a0.w);
        A_s[lk4 + 0][lrow + 64] = f2tf32(a1.x); A_s[lk4 + 1][lrow + 64] = f2tf32(a1.y);
        A_s[lk4 + 2][lrow + 64] = f2tf32(a1.z); A_s[lk4 + 3][lrow + 64] = f2tf32(a1.w);
        B_s[lk4 + 0][lrow] = f2tf32(b0.x); B_s[lk4 + 1][lrow] = f2tf32(b0.y);
        B_s[lk4 + 2][lrow] = f2tf32(b0.z); B_s[lk4 + 3][lrow] = f2tf32(b0.w);
        B_s[lk4 + 0][lrow + 64] = f2tf32(b1.x); B_s[lk4 + 1][lrow + 64] = f2tf32(b1.y);
        B_s[lk4 + 2][lrow + 64] = f2tf32(b1.z); B_s[lk4 + 3][lrow + 64] = f2tf32(b1.w);
        __syncthreads();

        #pragma unroll
        for (int ks = 0; ks < 2; ks++) {
            int kq = ks * 8 + lr;
            uint32_t afr[2][4];
            #pragma unroll
            for (int mt = 0; mt < 2; mt++) {
                int row = m_base + mt * 16 + lq;
                afr[mt][0] = A_s[kq][row];
                afr[mt][1] = A_s[kq][row + 8];
                afr[mt][2] = A_s[kq + 4][row];
                afr[mt][3] = A_s[kq + 4][row + 8];
            }
            uint32_t bfr[8][2];
            #pragma unroll
            for (int nt = 0; nt < 8; nt++) {
                int col = n_base + nt * 8 + lq;
                bfr[nt][0] = B_s[kq][col];
                bfr[nt][1] = B_s[kq + 4][col];
            }
            #pragma unroll
            for (int mt = 0; mt < 2; mt++)
                #pragma unroll
                for (int nt = 0; nt < 8; nt++)
                    mma_tf32(acc[mt][nt], afr[mt][0], afr[mt][1], afr[mt][2],
                             afr[mt][3], bfr[nt][0], bfr[nt][1]);
        }
    }

    // epilogue: add c, remap r=(t*B+b) -> (b*T+t), store float2 pairs
    #pragma unroll
    for (int nt = 0; nt < 8; nt++) {
        int col = n_base + nt * 8 + 2 * lr;
        float2 cv = *(const float2*)(cvec + v0 + col);
        #pragma unroll
        for (int mt = 0; mt < 2; mt++) {
            #pragma unroll
            for (int h = 0; h < 2; h++) {
                int r = r0 + m_base + mt * 16 + lq + h * 8;
                int orow = (r & 63) * Td + (r >> 6);   // b*T + t
                float2 o;
                o.x = acc[mt][nt][h * 2 + 0] + cv.x;
                o.y = acc[mt][nt][h * 2 + 1] + cv.y;
                *(float2*)(outp + (size_t)orow * Vd + v0 + col) = o;
            }
        }
    }
}

// ---------------------------------------------------------------------------
// K5: in-place log_softmax over rows of 4096. One block (256 thr) per row.
// ---------------------------------------------------------------------------
__global__ void logsoftmax_kernel(float* __restrict__ outp) {
    float* row = outp + (size_t)blockIdx.x * Vd;
    const int tid = threadIdx.x;
    const int lane = tid & 31;
    const int wid = tid >> 5;
    __shared__ float sred[8];

    float4 v[4];
    float mx = -1e30f;
    #pragma unroll
    for (int i = 0; i < 4; i++) {
        v[i] = *(const float4*)(row + (i * 256 + tid) * 4);
        mx = fmaxf(mx, fmaxf(fmaxf(v[i].x, v[i].y), fmaxf(v[i].z, v[i].w)));
    }
    #pragma unroll
    for (int o = 16; o; o >>= 1) mx = fmaxf(mx, __shfl_xor_sync(0xffffffffu, mx, o));
    if (lane == 0) sred[wid] = mx;
    __syncthreads();
    float m2 = sred[lane & 7];
    #pragma unroll
    for (int o = 4; o; o >>= 1) m2 = fmaxf(m2, __shfl_xor_sync(0xffffffffu, m2, o));
    mx = m2;
    __syncthreads();

    float sum = 0.0f;
    #pragma unroll
    for (int i = 0; i < 4; i++) {
        sum += expf(v[i].x - mx) + expf(v[i].y - mx)
             + expf(v[i].z - mx) + expf(v[i].w - mx);
    }
    #pragma unroll
    for (int o = 16; o; o >>= 1) sum += __shfl_xor_sync(0xffffffffu, sum, o);
    if (lane == 0) sred[wid] = sum;
    __syncthreads();
    float s2 = sred[lane & 7];
    #pragma unroll
    for (int o = 4; o; o >>= 1) s2 += __shfl_xor_sync(0xffffffffu, s2, o);

    float lse = mx + logf(s2);
    #pragma unroll
    for (int i = 0; i < 4; i++) {
        v[i].x -= lse; v[i].y -= lse; v[i].z -= lse; v[i].w -= lse;
        *(float4*)(row + (i * 256 + tid) * 4) = v[i];
    }
}

// ---------------------------------------------------------------------------
// K6: hiddens transpose  outh[h, r] = g_hs[r, h]   (r = t*B+b)
// ---------------------------------------------------------------------------
__global__ void transpose_kernel(float* __restrict__ outh) {
    __shared__ float tile[32][33];
    const int h0 = blockIdx.x * 32;
    const int r0 = blockIdx.y * 32;
    const int tx = threadIdx.x;
    const int ty = threadIdx.y;
    #pragma unroll
    for (int i = 0; i < 32; i += 8)
        tile[ty + i][tx] = g_hs[(size_t)(r0 + ty + i) * Hd + h0 + tx];
    __syncthreads();
    #pragma unroll
    for (int i = 0; i < 32; i += 8)
        outh[(size_t)(h0 + ty + i) * BT + r0 + tx] = tile[tx][ty + i];
}

// ---------------------------------------------------------------------------
extern "C" void kernel_launch(void* const* d_in, const int* in_sizes, int n_in,
                              void* d_out, int out_size) {
    const int*   X   = nullptr;
    const float* wxh = nullptr;
    const float* whh = nullptr;
    const float* wvh = nullptr;
    const float* bv  = nullptr;
    const float* cv  = nullptr;

    for (int i = 0; i < n_in; i++) {
        int s = in_sizes[i];
        if (s == BT && !X)            X   = (const int*)d_in[i];
        else if (s == Hd * Hd)        whh = (const float*)d_in[i];
        else if (s == Hd)             bv  = (const float*)d_in[i];
        else if (s == Vd)             cv  = (const float*)d_in[i];
        else if (s == Vd * Hd) {
            if (!wxh) wxh = (const float*)d_in[i];
            else      wvh = (const float*)d_in[i];
        }
    }

    float* outp = (float*)d_out;
    float* outs = outp;                       // (B, T, V) log-probs
    float* outh = outp + (size_t)BT * Vd;     // (H, T, B) hiddens

    // persistent kernel needs 192 KB dynamic smem (idempotent host call)
    const int rnn_smem = (8192 + 4096) * 16;  // 196,608 B
    cudaFuncSetAttribute(rnn_persistent,
                         cudaFuncAttributeMaxDynamicSharedMemorySize, rnn_smem);

    // 1) embedding gather + bias
    embed_kernel<<<BT, 256>>>(X, wxh, bv);
    // 2) recurrence: single persistent launch, 1024 threads (occ 50%)
    rnn_persistent<<<NBLK, 1024, rnn_smem>>>(whh);
    // 3) output projection on tf32 tensor cores (writes z with row remap)
    vh_gemm_tf32<<<dim3(Vd / 128, BT / 128), 256>>>(wvh, cv, outs);
    // 4) log_softmax in place
    logsoftmax_kernel<<<BT, 256>>>(outs);
    // 5) hiddens transpose
    transpose_kernel<<<dim3(Hd / 32, BT / 32), dim3(32, 8)>>>(outh);
}

// round 12
// speedup vs baseline: 1.3504x; 1.3504x over previous
#include <cuda_runtime.h>
#include <cuda_bf16.h>
#include <math.h>
#include <stdint.h>

// Problem constants
#define Hd 1024
#define Vd 4096
#define Bd 64
#define Td 512
#define BT (Bd*Td)       // 32768
#define BdHd (Bd*Hd)
#define NBLK 128         // 4 groups x 32 CTAs
#define GSZ 32           // CTAs per group
#define GROWS 16         // batch rows per group
#define JPC 32           // j columns per CTA

// smem u32 offsets (persistent kernel). Row stride 516 u32 (== 4 mod 32:
// fragment reads bank = 4*(l>>2) + (l&3) -> 32 distinct banks, conflict-free).
#define WSTR 516
#define OFF_WHI 0                       // wpack_hi: 32*516
#define OFF_WLO (32*WSTR)               // wpack_lo: 32*516
#define OFF_HHI (64*WSTR)               // hpack_hi: 16*516
#define OFF_HLO (80*WSTR)               // hpack_lo: 16*516
#define OFF_RED (96*WSTR)               // red: 16 warps * 128 floats
#define SMEM_U32 (96*WSTR + 2048)       // 51584 u32 = 206,336 B

// Scratch (device globals; no runtime allocation)
__device__ float g_abase[(size_t)BT*Hd];   // (t,b,h) pre-activation x_emb + b
__device__ float g_hs[(size_t)BT*Hd];      // (t,b,h) hidden states
__device__ unsigned g_gcnt[4*32];          // atomic start-barrier counters
__device__ unsigned g_ggen[4*32];          // atomic start-barrier generations
__device__ __align__(128) unsigned g_flags[4*32];  // per-group arrival flags

// bf16 two-term split helpers
__device__ __forceinline__ unsigned short bf16_of(float x) {
    __nv_bfloat16 b = __float2bfloat16(x);
    return *(unsigned short*)&b;
}
__device__ __forceinline__ float f_of_bf16(unsigned short u) {
    __nv_bfloat16 b = *(__nv_bfloat16*)&u;
    return __bfloat162float(b);
}
// split float4 (4 consecutive k) into 2 packed-hi u32 and 2 packed-lo u32
__device__ __forceinline__ void split4(float4 v, uint2& hi, uint2& lo) {
    unsigned short h0 = bf16_of(v.x), h1 = bf16_of(v.y),
                   h2 = bf16_of(v.z), h3 = bf16_of(v.w);
    unsigned short l0 = bf16_of(v.x - f_of_bf16(h0)),
                   l1 = bf16_of(v.y - f_of_bf16(h1)),
                   l2 = bf16_of(v.z - f_of_bf16(h2)),
                   l3 = bf16_of(v.w - f_of_bf16(h3));
    hi.x = ((unsigned)h1 << 16) | h0;  hi.y = ((unsigned)h3 << 16) | h2;
    lo.x = ((unsigned)l1 << 16) | l0;  lo.y = ((unsigned)l3 << 16) | l2;
}

__device__ __forceinline__ void mma_bf16(float c[4], uint32_t a0, uint32_t a1,
                                         uint32_t a2, uint32_t a3,
                                         uint32_t b0, uint32_t b1) {
    asm volatile(
        "mma.sync.aligned.m16n8k16.row.col.f32.bf16.bf16.f32 "
        "{%0,%1,%2,%3}, {%4,%5,%6,%7}, {%8,%9}, {%0,%1,%2,%3};"
        : "+f"(c[0]), "+f"(c[1]), "+f"(c[2]), "+f"(c[3])
        : "r"(a0), "r"(a1), "r"(a2), "r"(a3), "r"(b0), "r"(b1));
}

// ---------------------------------------------------------------------------
// K1: embedding gather + bias
// ---------------------------------------------------------------------------
__global__ void embed_kernel(const int* __restrict__ X,
                             const float* __restrict__ wxh,
                             const float* __restrict__ bvec) {
    int r = blockIdx.x;            // r = t*B + b
    int t = r >> 6;
    int b = r & 63;
    int row = X[b * Td + t];
    const float4* src = (const float4*)(wxh + (size_t)row * Hd);
    const float4* bb  = (const float4*)bvec;
    float4* dst = (float4*)(g_abase + (size_t)r * Hd);
    int i = threadIdx.x;
    float4 v = src[i];
    float4 w = bb[i];
    v.x += w.x; v.y += w.y; v.z += w.z; v.w += w.w;
    dst[i] = v;
}

// ---------------------------------------------------------------------------
// Atomic group barrier (launch-start only), replay-safe.
// ---------------------------------------------------------------------------
__device__ __forceinline__ void group_barrier_atomic(int tid, int grp) {
    __syncthreads();
    if (tid == 0) {
        unsigned* cnt = &g_gcnt[grp * 32];
        unsigned* gnp = &g_ggen[grp * 32];
        unsigned gen = *(volatile unsigned*)gnp;
        __threadfence();
        unsigned p = atomicAdd(cnt, 1u);
        if (p == GSZ - 1u) {
            atomicExch(cnt, 0u);
            __threadfence();
            atomicExch(gnp, gen + 1u);
        } else {
            while (*(volatile unsigned*)gnp == gen) { }
        }
        __threadfence();
    }
    __syncthreads();
}

// ---------------------------------------------------------------------------
// K2: persistent recurrence, bf16-split tensor-core step GEMM.
// Group g (32 CTAs) owns batch rows g*16..+16; CTA jc owns cols jc*32..+32.
// W slice split once into smem bf16 hi/lo (132 KB); per step h slice staged
// as packed bf16 hi/lo pairs (66 KB). 16 warps = 4(n-tile) x 4(K-chunk);
// each warp: 16 k-steps x 3 mma (hh, hl, lh) into one m16n8 c-fragment;
// 4-way cross-warp smem reduce; tanh; fp32 h store; flag barrier.
// ---------------------------------------------------------------------------
__global__ void __launch_bounds__(512, 1)
rnn_persistent(const float* __restrict__ whh) {
    extern __shared__ uint32_t dsm[];

    const int bid = blockIdx.x;     // 0..127
    const int grp = bid >> 5;       // 0..3
    const int jc  = bid & 31;       // 0..31
    const int j0  = jc * JPC;
    const int b0  = grp * GROWS;
    const int tid = threadIdx.x;
    const int ln  = tid & 31;
    const int w   = tid >> 5;       // warp 0..15
    const int nt  = w & 3;          // n-tile (8 j-cols each)
    const int kch = w >> 2;         // K-chunk (256 k each)

    // reset this CTA's arrival flag
    if (tid == 0) *(volatile unsigned*)&g_flags[grp * 32 + jc] = 0u;

    // one-time: load + split W_hh slice rows j0..j0+31 into smem bf16 hi/lo
    {
        const float4* wsrc = (const float4*)(whh + (size_t)j0 * Hd);
        #pragma unroll
        for (int q = 0; q < 16; q++) {
            int idx = tid + q * 512;            // 0..8191 f4 (32 rows x 256)
            int row = idx >> 8, f4c = idx & 255;
            float4 v = wsrc[idx];
            uint2 hi, lo;
            split4(v, hi, lo);
            *(uint2*)&dsm[OFF_WHI + row * WSTR + f4c * 2] = hi;
            *(uint2*)&dsm[OFF_WLO + row * WSTR + f4c * 2] = lo;
        }
    }

    // h_0 = tanh(a_base[0]) for this CTA's owned (b,j): 16x32 = 512 elems
    {
        int r = tid >> 5, cc = tid & 31;
        size_t off = (size_t)(b0 + r) * Hd + j0 + cc;
        g_hs[off] = tanhf(g_abase[off]);
    }

    group_barrier_atomic(tid, grp);

    // output decode: thread tid -> one of 512 outputs (16 b-rows x 32 j-cols)
    const int o_nt   = tid >> 7;            // 0..3
    const int o_l    = (tid & 127) >> 2;    // fragment lane 0..31
    const int o_creg = tid & 3;             // c-register 0..3
    const int o_row  = (o_l >> 2) + 8 * (o_creg >> 1);          // b-row 0..15
    const int o_col  = (o_l & 3) * 2 + (o_creg & 1);            // 0..7
    const int jo = j0 + o_nt * 8 + o_col;
    const int bo = b0 + o_row;

    // fragment lane geometry (compute phase)
    const int fr = ln >> 2;       // A row low / B n offset
    const int fc = ln & 3;        // k-pair offset

    volatile unsigned* myflag = &g_flags[grp * 32 + jc];
    volatile unsigned* pollflag = &g_flags[grp * 32 + ln];

    for (int t = 1; t < Td; t++) {
        const unsigned local = (unsigned)(t - 1);

        // prefetch a_base for this thread's output
        float abv = __ldg(&g_abase[(size_t)t * BdHd + (size_t)bo * Hd + jo]);

        // wait: all 32 group flags >= local (warp 0 polls one 128B line)
        if (tid < 32) {
            while (__any_sync(0xffffffffu, *pollflag < local)) { }
            __threadfence();                     // acquire
        }
        __syncthreads();

        // stage + split group's h_{t-1}: 4096 f4 (16 rows x 256), 8/thread
        {
            const float4* hsrc = (const float4*)(g_hs + (size_t)(t - 1) * BdHd
                                                      + (size_t)b0 * Hd);
            #pragma unroll
            for (int q = 0; q < 8; q++) {
                int idx = tid + q * 512;
                int row = idx >> 8, f4c = idx & 255;
                float4 v = hsrc[idx];
                uint2 hi, lo;
                split4(v, hi, lo);
                *(uint2*)&dsm[OFF_HHI + row * WSTR + f4c * 2] = hi;
                *(uint2*)&dsm[OFF_HLO + row * WSTR + f4c * 2] = lo;
            }
        }
        __syncthreads();

        // compute: warp (nt, kch): 16 k-steps x 3 mma into one c-fragment
        float c[4] = {0.0f, 0.0f, 0.0f, 0.0f};
        const uint32_t* HHI = dsm + OFF_HHI;
        const uint32_t* HLO = dsm + OFF_HLO;
        const uint32_t* WHI = dsm + OFF_WHI + (nt * 8 + fr) * WSTR;
        const uint32_t* WLO = dsm + OFF_WLO + (nt * 8 + fr) * WSTR;

        #pragma unroll
        for (int ks = 0; ks < 16; ks++) {
            const int kb = (kch * 16 + ks) * 8 + fc;  // pair-unit base
            uint32_t ah0 = HHI[fr * WSTR + kb];
            uint32_t ah1 = HHI[(fr + 8) * WSTR + kb];
            uint32_t ah2 = HHI[fr * WSTR + kb + 4];
            uint32_t ah3 = HHI[(fr + 8) * WSTR + kb + 4];
            uint32_t al0 = HLO[fr * WSTR + kb];
            uint32_t al1 = HLO[(fr + 8) * WSTR + kb];
            uint32_t al2 = HLO[fr * WSTR + kb + 4];
            uint32_t al3 = HLO[(fr + 8) * WSTR + kb + 4];
            uint32_t bh0 = WHI[kb];
            uint32_t bh1 = WHI[kb + 4];
            uint32_t bl0 = WLO[kb];
            uint32_t bl1 = WLO[kb + 4];
            mma_bf16(c, ah0, ah1, ah2, ah3, bh0, bh1);   // hi*hi
            mma_bf16(c, ah0, ah1, ah2, ah3, bl0, bl1);   // hi*lo
            mma_bf16(c, al0, al1, al2, al3, bh0, bh1);   // lo*hi
        }

        // write partials: red[w][lane][0..3] (float4, conflict-free)
        *(float4*)&dsm[OFF_RED + w * 128 + ln * 4] =
            make_float4(c[0], c[1], c[2], c[3]);
        __syncthreads();

        // reduce 4 K-chunk warps, add a_base, tanh, store h_t (1/thread)
        {
            const float* red = (const float*)&dsm[OFF_RED];
            int pos = (tid & 127);
            float s = abv;
            #pragma unroll
            for (int kc = 0; kc < 4; kc++)
                s += red[(kc * 4 + o_nt) * 128 + pos];
            g_hs[(size_t)t * BdHd + (size_t)bo * Hd + jo] = tanhf(s);
        }

        // arrive: CTA's h_t stores done -> post flag
        __syncthreads();
        if (tid == 0) {
            __threadfence();
            *myflag = local + 1u;
        }
    }
}

// ---------------------------------------------------------------------------
// K4: output GEMM on tf32 tensor cores (unchanged from R8).
// ---------------------------------------------------------------------------
__device__ __forceinline__ uint32_t f2tf32(float x) {
    uint32_t r;
    asm("cvt.rna.tf32.f32 %0, %1;" : "=r"(r) : "f"(x));
    return r;
}
__device__ __forceinline__ void mma_tf32(float c[4], uint32_t a0, uint32_t a1,
                                         uint32_t a2, uint32_t a3,
                                         uint32_t b0, uint32_t b1) {
    asm volatile(
        "mma.sync.aligned.m16n8k8.row.col.f32.tf32.tf32.f32 "
        "{%0,%1,%2,%3}, {%4,%5,%6,%7}, {%8,%9}, {%0,%1,%2,%3};"
        : "+f"(c[0]), "+f"(c[1]), "+f"(c[2]), "+f"(c[3])
        : "r"(a0), "r"(a1), "r"(a2), "r"(a3), "r"(b0), "r"(b1));
}

#define LDA 136

__global__ void __launch_bounds__(256, 1)
vh_gemm_tf32(const float* __restrict__ wvh,
             const float* __restrict__ cvec,
             float* __restrict__ outp) {
    __shared__ uint32_t A_s[16][LDA];
    __shared__ uint32_t B_s[16][LDA];
    const int v0 = blockIdx.x * 128;
    const int r0 = blockIdx.y * 128;
    const int tid  = threadIdx.x;
    const int warp = tid >> 5;
    const int lane = tid & 31;
    const int warp_m = warp & 3;
    const int warp_n = warp >> 2;
    const int m_base = warp_m * 32;
    const int n_base = warp_n * 64;
    const int lq = lane >> 2;
    const int lr = lane & 3;

    float acc[2][8][4];
    #pragma unroll
    for (int mt = 0; mt < 2; mt++)
        #pragma unroll
        for (int ntl = 0; ntl < 8; ntl++)
            #pragma unroll
            for (int e = 0; e < 4; e++) acc[mt][ntl][e] = 0.0f;

    const int lrow = tid >> 2;
    const int lk4  = (tid & 3) * 4;

    for (int kc = 0; kc < 64; ++kc) {
        int k0 = kc * 16;
        float4 a0 = *(const float4*)(g_hs + (size_t)(r0 + lrow) * Hd + k0 + lk4);
        float4 a1 = *(const float4*)(g_hs + (size_t)(r0 + lrow + 64) * Hd + k0 + lk4);
        float4 b0 = *(const float4*)(wvh + (size_t)(v0 + lrow) * Hd + k0 + lk4);
        float4 b1 = *(const float4*)(wvh + (size_t)(v0 + lrow + 64) * Hd + k0 + lk4);
        __syncthreads();
        A_s[lk4 + 0][lrow] = f2tf32(a0.x); A_s[lk4 + 1][lrow] = f2tf32(a0.y);
        A_s[lk4 + 2][lrow] = f2tf32(a0.z); A_s[lk4 + 3][lrow] = f2tf32(a0.w);
        A_s[lk4 + 0][lrow + 64] = f2tf32(a1.x); A_s[lk4 + 1][lrow + 64] = f2tf32(a1.y);
        A_s[lk4 + 2][lrow + 64] = f2tf32(a1.z); A_s[lk4 + 3][lrow + 64] = f2tf32(a1.w);
        B_s[lk4 + 0][lrow] = f2tf32(b0.x); B_s[lk4 + 1][lrow] = f2tf32(b0.y);
        B_s[lk4 + 2][lrow] = f2tf32(b0.z); B_s[lk4 + 3][lrow] = f2tf32(b0.w);
        B_s[lk4 + 0][lrow + 64] = f2tf32(b1.x); B_s[lk4 + 1][lrow + 64] = f2tf32(b1.y);
        B_s[lk4 + 2][lrow + 64] = f2tf32(b1.z); B_s[lk4 + 3][lrow + 64] = f2tf32(b1.w);
        __syncthreads();

        #pragma unroll
        for (int ks = 0; ks < 2; ks++) {
            int kq = ks * 8 + lr;
            uint32_t afr[2][4];
            #pragma unroll
            for (int mt = 0; mt < 2; mt++) {
                int row = m_base + mt * 16 + lq;
                afr[mt][0] = A_s[kq][row];
                afr[mt][1] = A_s[kq][row + 8];
                afr[mt][2] = A_s[kq + 4][row];
                afr[mt][3] = A_s[kq + 4][row + 8];
            }
            uint32_t bfr[8][2];
            #pragma unroll
            for (int ntl = 0; ntl < 8; ntl++) {
                int col = n_base + ntl * 8 + lq;
                bfr[ntl][0] = B_s[kq][col];
                bfr[ntl][1] = B_s[kq + 4][col];
            }
            #pragma unroll
            for (int mt = 0; mt < 2; mt++)
                #pragma unroll
                for (int ntl = 0; ntl < 8; ntl++)
                    mma_tf32(acc[mt][ntl], afr[mt][0], afr[mt][1], afr[mt][2],
                             afr[mt][3], bfr[ntl][0], bfr[ntl][1]);
        }
    }

    #pragma unroll
    for (int ntl = 0; ntl < 8; ntl++) {
        int col = n_base + ntl * 8 + 2 * lr;
        float2 cv = *(const float2*)(cvec + v0 + col);
        #pragma unroll
        for (int mt = 0; mt < 2; mt++) {
            #pragma unroll
            for (int h = 0; h < 2; h++) {
                int r = r0 + m_base + mt * 16 + lq + h * 8;
                int orow = (r & 63) * Td + (r >> 6);
                float2 o;
                o.x = acc[mt][ntl][h * 2 + 0] + cv.x;
                o.y = acc[mt][ntl][h * 2 + 1] + cv.y;
                *(float2*)(outp + (size_t)orow * Vd + v0 + col) = o;
            }
        }
    }
}

// ---------------------------------------------------------------------------
// K5: in-place log_softmax (unchanged)
// ---------------------------------------------------------------------------
__global__ void logsoftmax_kernel(float* __restrict__ outp) {
    float* row = outp + (size_t)blockIdx.x * Vd;
    const int tid = threadIdx.x;
    const int lane = tid & 31;
    const int wid = tid >> 5;
    __shared__ float sred[8];

    float4 v[4];
    float mx = -1e30f;
    #pragma unroll
    for (int i = 0; i < 4; i++) {
        v[i] = *(const float4*)(row + (i * 256 + tid) * 4);
        mx = fmaxf(mx, fmaxf(fmaxf(v[i].x, v[i].y), fmaxf(v[i].z, v[i].w)));
    }
    #pragma unroll
    for (int o = 16; o; o >>= 1) mx = fmaxf(mx, __shfl_xor_sync(0xffffffffu, mx, o));
    if (lane == 0) sred[wid] = mx;
    __syncthreads();
    float m2 = sred[lane & 7];
    #pragma unroll
    for (int o = 4; o; o >>= 1) m2 = fmaxf(m2, __shfl_xor_sync(0xffffffffu, m2, o));
    mx = m2;
    __syncthreads();

    float sum = 0.0f;
    #pragma unroll
    for (int i = 0; i < 4; i++) {
        sum += expf(v[i].x - mx) + expf(v[i].y - mx)
             + expf(v[i].z - mx) + expf(v[i].w - mx);
    }
    #pragma unroll
    for (int o = 16; o; o >>= 1) sum += __shfl_xor_sync(0xffffffffu, sum, o);
    if (lane == 0) sred[wid] = sum;
    __syncthreads();
    float s2 = sred[lane & 7];
    #pragma unroll
    for (int o = 4; o; o >>= 1) s2 += __shfl_xor_sync(0xffffffffu, s2, o);

    float lse = mx + logf(s2);
    #pragma unroll
    for (int i = 0; i < 4; i++) {
        v[i].x -= lse; v[i].y -= lse; v[i].z -= lse; v[i].w -= lse;
        *(float4*)(row + (i * 256 + tid) * 4) = v[i];
    }
}

// ---------------------------------------------------------------------------
// K6: hiddens transpose (unchanged)
// ---------------------------------------------------------------------------
__global__ void transpose_kernel(float* __restrict__ outh) {
    __shared__ float tile[32][33];
    const int h0 = blockIdx.x * 32;
    const int r0 = blockIdx.y * 32;
    const int tx = threadIdx.x;
    const int ty = threadIdx.y;
    #pragma unroll
    for (int i = 0; i < 32; i += 8)
        tile[ty + i][tx] = g_hs[(size_t)(r0 + ty + i) * Hd + h0 + tx];
    __syncthreads();
    #pragma unroll
    for (int i = 0; i < 32; i += 8)
        outh[(size_t)(h0 + ty + i) * BT + r0 + tx] = tile[tx][ty + i];
}

// ---------------------------------------------------------------------------
extern "C" void kernel_launch(void* const* d_in, const int* in_sizes, int n_in,
                              void* d_out, int out_size) {
    const int*   X   = nullptr;
    const float* wxh = nullptr;
    const float* whh = nullptr;
    const float* wvh = nullptr;
    const float* bv  = nullptr;
    const float* cv  = nullptr;

    for (int i = 0; i < n_in; i++) {
        int s = in_sizes[i];
        if (s == BT && !X)            X   = (const int*)d_in[i];
        else if (s == Hd * Hd)        whh = (const float*)d_in[i];
        else if (s == Hd)             bv  = (const float*)d_in[i];
        else if (s == Vd)             cv  = (const float*)d_in[i];
        else if (s == Vd * Hd) {
            if (!wxh) wxh = (const float*)d_in[i];
            else      wvh = (const float*)d_in[i];
        }
    }

    float* outp = (float*)d_out;
    float* outs = outp;                       // (B, T, V) log-probs
    float* outh = outp + (size_t)BT * Vd;     // (H, T, B) hiddens

    const int rnn_smem = SMEM_U32 * 4;        // 206,336 B
    cudaFuncSetAttribute(rnn_persistent,
                         cudaFuncAttributeMaxDynamicSharedMemorySize, rnn_smem);

    // 1) embedding gather + bias
    embed_kernel<<<BT, 256>>>(X, wxh, bv);
    // 2) recurrence: bf16-split tensor-core step GEMM, 512 thr, single launch
    rnn_persistent<<<NBLK, 512, rnn_smem>>>(whh);
    // 3) output projection on tf32 tensor cores
    vh_gemm_tf32<<<dim3(Vd / 128, BT / 128), 256>>>(wvh, cv, outs);
    // 4) log_softmax in place
    logsoftmax_kernel<<<BT, 256>>>(outs);
    // 5) hiddens transpose
    transpose_kernel<<<dim3(Hd / 32, BT / 32), dim3(32, 8)>>>(outh);
}